// round 3
// baseline (speedup 1.0000x reference)
#include <cuda_runtime.h>
#include <cuda_bf16.h>
#include <mma.h>

using namespace nvcuda;

#define B_    8192
#define NNEG  8192
#define D_    1024

__device__ __align__(16) __nv_bfloat16 g_Qh[(size_t)B_ * D_];   // 16 MB normalized Q (bf16)
__device__ __align__(16) __nv_bfloat16 g_Nh[(size_t)NNEG * D_]; // 16 MB normalized N (bf16)
__device__ float g_pos[B_];                                     // pos_sim per row
__device__ float g_part[(size_t)B_ * 64];                       // per (row, n-tile) partial exp-sums

__constant__ float c_invT = 1.0f / 0.92f;

// ---------------------------------------------------------------------------
// Kernel 1: per-row ||q||, ||p||, q.p  -> pos_sim, normalized bf16 Q
// grid = B_, block = 256 (each thread owns one float4 of the 1024-dim row)
// ---------------------------------------------------------------------------
__global__ void k_norm_qp(const float* __restrict__ q, const float* __restrict__ p) {
    int b = blockIdx.x, t = threadIdx.x;
    float4 a = reinterpret_cast<const float4*>(q + (size_t)b * D_)[t];
    float4 c = reinterpret_cast<const float4*>(p + (size_t)b * D_)[t];

    float qq = a.x*a.x + a.y*a.y + a.z*a.z + a.w*a.w;
    float pp = c.x*c.x + c.y*c.y + c.z*c.z + c.w*c.w;
    float qp = a.x*c.x + a.y*c.y + a.z*c.z + a.w*c.w;

    #pragma unroll
    for (int o = 16; o > 0; o >>= 1) {
        qq += __shfl_xor_sync(0xffffffffu, qq, o);
        pp += __shfl_xor_sync(0xffffffffu, pp, o);
        qp += __shfl_xor_sync(0xffffffffu, qp, o);
    }
    __shared__ float sq[8], sp[8], sc[8];
    __shared__ float s_inv;
    int w = t >> 5, l = t & 31;
    if (l == 0) { sq[w] = qq; sp[w] = pp; sc[w] = qp; }
    __syncthreads();
    if (t == 0) {
        float QQ = 0.f, PP = 0.f, QP = 0.f;
        #pragma unroll
        for (int i = 0; i < 8; i++) { QQ += sq[i]; PP += sp[i]; QP += sc[i]; }
        float qn = sqrtf(QQ), pn = sqrtf(PP);
        g_pos[b] = QP / fmaxf(qn * pn, 1e-6f);
        s_inv = (qn > 0.f) ? (1.0f / qn) : 0.f;
    }
    __syncthreads();
    float inv = s_inv;
    __nv_bfloat162 lo = __floats2bfloat162_rn(a.x * inv, a.y * inv);
    __nv_bfloat162 hi = __floats2bfloat162_rn(a.z * inv, a.w * inv);
    __nv_bfloat162* dst = reinterpret_cast<__nv_bfloat162*>(g_Qh) + (size_t)b * (D_ / 2) + t * 2;
    dst[0] = lo; dst[1] = hi;
}

// ---------------------------------------------------------------------------
// Kernel 2: per-row ||n|| -> normalized bf16 N
// ---------------------------------------------------------------------------
__global__ void k_norm_n(const float* __restrict__ n) {
    int b = blockIdx.x, t = threadIdx.x;
    float4 a = reinterpret_cast<const float4*>(n + (size_t)b * D_)[t];
    float nn = a.x*a.x + a.y*a.y + a.z*a.z + a.w*a.w;
    #pragma unroll
    for (int o = 16; o > 0; o >>= 1) nn += __shfl_xor_sync(0xffffffffu, nn, o);
    __shared__ float sn[8];
    __shared__ float s_inv;
    int w = t >> 5, l = t & 31;
    if (l == 0) sn[w] = nn;
    __syncthreads();
    if (t == 0) {
        float NN = 0.f;
        #pragma unroll
        for (int i = 0; i < 8; i++) NN += sn[i];
        float qn = sqrtf(NN);
        s_inv = (qn > 0.f) ? (1.0f / qn) : 0.f;
    }
    __syncthreads();
    float inv = s_inv;
    __nv_bfloat162 lo = __floats2bfloat162_rn(a.x * inv, a.y * inv);
    __nv_bfloat162 hi = __floats2bfloat162_rn(a.z * inv, a.w * inv);
    __nv_bfloat162* dst = reinterpret_cast<__nv_bfloat162*>(g_Nh) + (size_t)b * (D_ / 2) + t * 2;
    dst[0] = lo; dst[1] = hi;
}

// ---------------------------------------------------------------------------
// Polynomial exp on [-1.09, 1.09]: degree-9 Taylor, FMA-pipe only (no MUFU).
// Max abs error ~2e-6 — far below the bf16 GEMM noise floor.
// ---------------------------------------------------------------------------
__device__ __forceinline__ float poly_exp(float x) {
    float e = 2.7557319e-6f;            // 1/9!
    e = fmaf(e, x, 2.4801587e-5f);      // 1/8!
    e = fmaf(e, x, 1.9841270e-4f);      // 1/7!
    e = fmaf(e, x, 1.3888889e-3f);      // 1/6!
    e = fmaf(e, x, 8.3333333e-3f);      // 1/5!
    e = fmaf(e, x, 4.1666668e-2f);      // 1/4!
    e = fmaf(e, x, 1.6666667e-1f);      // 1/3!
    e = fmaf(e, x, 0.5f);               // 1/2!
    e = fmaf(e, x, 1.0f);
    e = fmaf(e, x, 1.0f);
    return e;
}

// ---------------------------------------------------------------------------
// Kernel 3: bf16 wmma GEMM tile (64 x 128) over K=1024, fused exp + row sums.
// grid = (NNEG/128, B_/64), block = 256 (8 warps as 2x4 of 32x32 warp tiles)
// ---------------------------------------------------------------------------
__global__ void k_gemm() {
    constexpr int BM = 64, BN = 128, BK = 32;
    __shared__ __align__(16) __nv_bfloat16 As[BM][BK];
    __shared__ __align__(16) __nv_bfloat16 Bs[BN][BK];
    __shared__ __align__(16) float Cb[BM][BN + 4];   // +4 pad (stride 132)

    const int bx = blockIdx.x;   // n-tile (0..63)
    const int by = blockIdx.y;   // b-tile (0..127)
    const int t  = threadIdx.x;
    const int warp = t >> 5;
    const int wm = warp >> 2;    // 0..1  (rows)
    const int wn = warp & 3;     // 0..3  (cols)

    wmma::fragment<wmma::accumulator, 16, 16, 16, float> acc[2][2];
    #pragma unroll
    for (int i = 0; i < 2; i++)
        #pragma unroll
        for (int j = 0; j < 2; j++)
            wmma::fill_fragment(acc[i][j], 0.0f);

    const __nv_bfloat16* Aptr = g_Qh + (size_t)by * BM * D_;
    const __nv_bfloat16* Bptr = g_Nh + (size_t)bx * BN * D_;

    const int arow = t >> 2, ac4 = t & 3;   // A: 64 rows x 4 uint4 = 256 loads

    for (int k0 = 0; k0 < D_; k0 += BK) {
        reinterpret_cast<uint4*>(&As[arow][0])[ac4] =
            reinterpret_cast<const uint4*>(Aptr + (size_t)arow * D_ + k0)[ac4];
        #pragma unroll
        for (int r = 0; r < 2; r++) {
            int idx = t + r * 256;
            int brow = idx >> 2, bc4 = idx & 3;
            reinterpret_cast<uint4*>(&Bs[brow][0])[bc4] =
                reinterpret_cast<const uint4*>(Bptr + (size_t)brow * D_ + k0)[bc4];
        }
        __syncthreads();

        #pragma unroll
        for (int kk = 0; kk < BK; kk += 16) {
            wmma::fragment<wmma::matrix_a, 16, 16, 16, __nv_bfloat16, wmma::row_major> af[2];
            wmma::fragment<wmma::matrix_b, 16, 16, 16, __nv_bfloat16, wmma::col_major> bfg[2];
            wmma::load_matrix_sync(af[0], &As[wm * 32][kk], BK);
            wmma::load_matrix_sync(af[1], &As[wm * 32 + 16][kk], BK);
            wmma::load_matrix_sync(bfg[0], &Bs[wn * 32][kk], BK);
            wmma::load_matrix_sync(bfg[1], &Bs[wn * 32 + 16][kk], BK);
            #pragma unroll
            for (int i = 0; i < 2; i++)
                #pragma unroll
                for (int j = 0; j < 2; j++)
                    wmma::mma_sync(acc[i][j], af[i], bfg[j], acc[i][j]);
        }
        __syncthreads();
    }

    #pragma unroll
    for (int i = 0; i < 2; i++)
        #pragma unroll
        for (int j = 0; j < 2; j++)
            wmma::store_matrix_sync(&Cb[wm * 32 + 16 * i][wn * 32 + 16 * j],
                                    acc[i][j], BN + 4, wmma::mem_row_major);
    __syncthreads();

    // Fused exp + row partial sums: 4 threads per row, 32 cols each.
    const int row = t >> 2, seg = t & 3;
    float s = 0.f;
    #pragma unroll
    for (int j = 0; j < 32; j++) {
        float x = Cb[row][seg * 32 + j] * c_invT;
        s += poly_exp(x);
    }
    s += __shfl_xor_sync(0xffffffffu, s, 1);
    s += __shfl_xor_sync(0xffffffffu, s, 2);
    if (seg == 0)
        g_part[(size_t)(by * 64 + row) * 64 + bx] = s;  // deterministic, no atomics
}

// ---------------------------------------------------------------------------
// Kernel 4: final reduction -> scalar loss
// ---------------------------------------------------------------------------
__global__ void k_final(float* __restrict__ out) {
    int t = threadIdx.x;
    double acc = 0.0;
    for (int b = t; b < B_; b += 256) {
        const float* pr = &g_part[(size_t)b * 64];
        float s2s = 0.f;
        #pragma unroll
        for (int j = 0; j < 64; j++) s2s += pr[j];
        float s2 = s2s * (1.0f / (float)NNEG);
        float s1 = expf(g_pos[b] * c_invT);
        acc += (double)log1pf(s2 / s1);   // -log(s1/(s1+s2))
    }
    #pragma unroll
    for (int o = 16; o > 0; o >>= 1) acc += __shfl_xor_sync(0xffffffffu, acc, o);
    __shared__ double sd[8];
    if ((t & 31) == 0) sd[t >> 5] = acc;
    __syncthreads();
    if (t == 0) {
        double tot = 0.0;
        #pragma unroll
        for (int i = 0; i < 8; i++) tot += sd[i];
        out[0] = (float)(tot / (double)B_);
    }
}

// ---------------------------------------------------------------------------
extern "C" void kernel_launch(void* const* d_in, const int* in_sizes, int n_in,
                              void* d_out, int out_size) {
    const float* q = (const float*)d_in[0];
    const float* p = (const float*)d_in[1];
    const float* n = (const float*)d_in[2];
    float* out = (float*)d_out;

    k_norm_qp<<<B_, 256>>>(q, p);
    k_norm_n<<<NNEG, 256>>>(n);
    k_gemm<<<dim3(NNEG / 128, B_ / 64), 256>>>();
    k_final<<<1, 256>>>(out);
}

// round 4
// speedup vs baseline: 3.0889x; 3.0889x over previous
#include <cuda_runtime.h>
#include <cuda_bf16.h>
#include <mma.h>

using namespace nvcuda;

#define B_    8192
#define NNEG  8192
#define D_    1024

__device__ __align__(16) __nv_bfloat16 g_Qh[(size_t)B_ * D_];   // 16 MB normalized Q (bf16)
__device__ __align__(16) __nv_bfloat16 g_Nh[(size_t)NNEG * D_]; // 16 MB normalized N (bf16)
__device__ float g_pos[B_];                                     // pos_sim per row
__device__ float g_part[(size_t)B_ * 64];                       // per (row, n-tile) partial exp-sums
__device__ float g_row[B_];                                     // per-row loss term

__constant__ float c_invT = 1.0f / 0.92f;

// ---------------------------------------------------------------------------
// Kernel 1: per-row ||q||, ||p||, q.p  -> pos_sim, normalized bf16 Q
// ---------------------------------------------------------------------------
__global__ void k_norm_qp(const float* __restrict__ q, const float* __restrict__ p) {
    int b = blockIdx.x, t = threadIdx.x;
    float4 a = reinterpret_cast<const float4*>(q + (size_t)b * D_)[t];
    float4 c = reinterpret_cast<const float4*>(p + (size_t)b * D_)[t];

    float qq = a.x*a.x + a.y*a.y + a.z*a.z + a.w*a.w;
    float pp = c.x*c.x + c.y*c.y + c.z*c.z + c.w*c.w;
    float qp = a.x*c.x + a.y*c.y + a.z*c.z + a.w*c.w;

    #pragma unroll
    for (int o = 16; o > 0; o >>= 1) {
        qq += __shfl_xor_sync(0xffffffffu, qq, o);
        pp += __shfl_xor_sync(0xffffffffu, pp, o);
        qp += __shfl_xor_sync(0xffffffffu, qp, o);
    }
    __shared__ float sq[8], sp[8], sc[8];
    __shared__ float s_inv;
    int w = t >> 5, l = t & 31;
    if (l == 0) { sq[w] = qq; sp[w] = pp; sc[w] = qp; }
    __syncthreads();
    if (t == 0) {
        float QQ = 0.f, PP = 0.f, QP = 0.f;
        #pragma unroll
        for (int i = 0; i < 8; i++) { QQ += sq[i]; PP += sp[i]; QP += sc[i]; }
        float qn = sqrtf(QQ), pn = sqrtf(PP);
        g_pos[b] = QP / fmaxf(qn * pn, 1e-6f);
        s_inv = (qn > 0.f) ? (1.0f / qn) : 0.f;
    }
    __syncthreads();
    float inv = s_inv;
    __nv_bfloat162 lo = __floats2bfloat162_rn(a.x * inv, a.y * inv);
    __nv_bfloat162 hi = __floats2bfloat162_rn(a.z * inv, a.w * inv);
    __nv_bfloat162* dst = reinterpret_cast<__nv_bfloat162*>(g_Qh) + (size_t)b * (D_ / 2) + t * 2;
    dst[0] = lo; dst[1] = hi;
}

// ---------------------------------------------------------------------------
// Kernel 2: per-row ||n|| -> normalized bf16 N
// ---------------------------------------------------------------------------
__global__ void k_norm_n(const float* __restrict__ n) {
    int b = blockIdx.x, t = threadIdx.x;
    float4 a = reinterpret_cast<const float4*>(n + (size_t)b * D_)[t];
    float nn = a.x*a.x + a.y*a.y + a.z*a.z + a.w*a.w;
    #pragma unroll
    for (int o = 16; o > 0; o >>= 1) nn += __shfl_xor_sync(0xffffffffu, nn, o);
    __shared__ float sn[8];
    __shared__ float s_inv;
    int w = t >> 5, l = t & 31;
    if (l == 0) sn[w] = nn;
    __syncthreads();
    if (t == 0) {
        float NN = 0.f;
        #pragma unroll
        for (int i = 0; i < 8; i++) NN += sn[i];
        float qn = sqrtf(NN);
        s_inv = (qn > 0.f) ? (1.0f / qn) : 0.f;
    }
    __syncthreads();
    float inv = s_inv;
    __nv_bfloat162 lo = __floats2bfloat162_rn(a.x * inv, a.y * inv);
    __nv_bfloat162 hi = __floats2bfloat162_rn(a.z * inv, a.w * inv);
    __nv_bfloat162* dst = reinterpret_cast<__nv_bfloat162*>(g_Nh) + (size_t)b * (D_ / 2) + t * 2;
    dst[0] = lo; dst[1] = hi;
}

// ---------------------------------------------------------------------------
// Polynomial exp on [-1.09, 1.09]: degree-9 Taylor, FMA-pipe only (no MUFU).
// ---------------------------------------------------------------------------
__device__ __forceinline__ float poly_exp(float x) {
    float e = 2.7557319e-6f;
    e = fmaf(e, x, 2.4801587e-5f);
    e = fmaf(e, x, 1.9841270e-4f);
    e = fmaf(e, x, 1.3888889e-3f);
    e = fmaf(e, x, 8.3333333e-3f);
    e = fmaf(e, x, 4.1666668e-2f);
    e = fmaf(e, x, 1.6666667e-1f);
    e = fmaf(e, x, 0.5f);
    e = fmaf(e, x, 1.0f);
    e = fmaf(e, x, 1.0f);
    return e;
}

// ---------------------------------------------------------------------------
// cp.async helpers (LDGSTS 16B)
// ---------------------------------------------------------------------------
__device__ __forceinline__ void cpa16(void* dst_smem, const void* src_gmem) {
    unsigned sd = (unsigned)__cvta_generic_to_shared(dst_smem);
    asm volatile("cp.async.cg.shared.global [%0], [%1], 16;\n" :: "r"(sd), "l"(src_gmem));
}
__device__ __forceinline__ void cp_commit() { asm volatile("cp.async.commit_group;\n"); }
__device__ __forceinline__ void cp_wait1()  { asm volatile("cp.async.wait_group 1;\n"); }

// ---------------------------------------------------------------------------
// Kernel 3: pipelined bf16 wmma GEMM, 128x128 tile, BK=64, double-buffered
// cp.async. Fused poly-exp + per-row partial sums.
// grid = (NNEG/128, B_/128), block = 256 (8 warps as 4x2 of 32x64 warp tiles)
// ---------------------------------------------------------------------------
#define BM 128
#define BN 128
#define BK 64
#define LDA 72           // BK + 8 bf16 pad (16B), row stride 144B
#define NIT (D_ / BK)    // 16

__global__ __launch_bounds__(256, 2) void k_gemm() {
    extern __shared__ __align__(16) char smem_raw[];
    __nv_bfloat16* As = reinterpret_cast<__nv_bfloat16*>(smem_raw);             // [2][BM*LDA]
    __nv_bfloat16* Bs = As + 2 * BM * LDA;                                       // [2][BN*LDA]
    float* Cb = reinterpret_cast<float*>(smem_raw);                              // epilogue reuse, stride 132

    const int bx = blockIdx.x;   // n-tile
    const int by = blockIdx.y;   // b-tile
    const int t  = threadIdx.x;
    const int warp = t >> 5;
    const int wm = warp >> 1;    // 0..3 (32-row strip)
    const int wn = warp & 1;     // 0..1 (64-col strip)

    const __nv_bfloat16* Aptr = g_Qh + (size_t)by * BM * D_;
    const __nv_bfloat16* Bptr = g_Nh + (size_t)bx * BN * D_;

    // each thread copies 4 A-chunks + 4 B-chunks of 16B per stage
    const int c_row[4] = { (t          ) >> 3, (t + 256) >> 3, (t + 512) >> 3, (t + 768) >> 3 };
    const int c_col   = (t & 7) * 8;   // bf16 offset within 64-wide K slice

    auto load_stage = [&](int s, int k0) {
        #pragma unroll
        for (int i = 0; i < 4; i++) {
            int r = c_row[i];
            cpa16(&As[s * BM * LDA + r * LDA + c_col], Aptr + (size_t)r * D_ + k0 + c_col);
            cpa16(&Bs[s * BN * LDA + r * LDA + c_col], Bptr + (size_t)r * D_ + k0 + c_col);
        }
    };

    wmma::fragment<wmma::accumulator, 16, 16, 16, float> acc[2][4];
    #pragma unroll
    for (int i = 0; i < 2; i++)
        #pragma unroll
        for (int j = 0; j < 4; j++)
            wmma::fill_fragment(acc[i][j], 0.0f);

    load_stage(0, 0);
    cp_commit();

    for (int it = 0; it < NIT; it++) {
        int cur = it & 1;
        if (it + 1 < NIT) load_stage(cur ^ 1, (it + 1) * BK);
        cp_commit();
        cp_wait1();
        __syncthreads();

        const __nv_bfloat16* Ab = As + cur * BM * LDA;
        const __nv_bfloat16* Bb = Bs + cur * BN * LDA;
        #pragma unroll
        for (int kk = 0; kk < BK; kk += 16) {
            wmma::fragment<wmma::matrix_a, 16, 16, 16, __nv_bfloat16, wmma::row_major> af[2];
            wmma::fragment<wmma::matrix_b, 16, 16, 16, __nv_bfloat16, wmma::col_major> bfg[4];
            wmma::load_matrix_sync(af[0], Ab + (wm * 32     ) * LDA + kk, LDA);
            wmma::load_matrix_sync(af[1], Ab + (wm * 32 + 16) * LDA + kk, LDA);
            #pragma unroll
            for (int j = 0; j < 4; j++)
                wmma::load_matrix_sync(bfg[j], Bb + (wn * 64 + 16 * j) * LDA + kk, LDA);
            #pragma unroll
            for (int i = 0; i < 2; i++)
                #pragma unroll
                for (int j = 0; j < 4; j++)
                    wmma::mma_sync(acc[i][j], af[i], bfg[j], acc[i][j]);
        }
        __syncthreads();
    }

    // Epilogue: dump accumulators to smem (reusing the A/B buffers)
    #pragma unroll
    for (int i = 0; i < 2; i++)
        #pragma unroll
        for (int j = 0; j < 4; j++)
            wmma::store_matrix_sync(&Cb[(wm * 32 + 16 * i) * 132 + wn * 64 + 16 * j],
                                    acc[i][j], 132, wmma::mem_row_major);
    __syncthreads();

    // exp + row partial sums: 2 threads per row, 64 cols each
    const int row = t >> 1, half = t & 1;
    const float* cr = &Cb[row * 132 + half * 64];
    float s = 0.f;
    #pragma unroll
    for (int j = 0; j < 64; j++)
        s += poly_exp(cr[j] * c_invT);
    s += __shfl_xor_sync(0xffffffffu, s, 1);
    if (half == 0)
        g_part[(size_t)(by * BM + row) * 64 + bx] = s;  // deterministic, no atomics
}

// ---------------------------------------------------------------------------
// Kernel 4a: per-row loss term (wide: 8192 threads)
// ---------------------------------------------------------------------------
__global__ void k_rowloss() {
    int b = blockIdx.x * 256 + threadIdx.x;
    const float4* pr = reinterpret_cast<const float4*>(&g_part[(size_t)b * 64]);
    float s2s = 0.f;
    #pragma unroll
    for (int j = 0; j < 16; j++) {
        float4 v = pr[j];
        s2s += v.x + v.y + v.z + v.w;
    }
    float s2 = s2s * (1.0f / (float)NNEG);
    float s1 = expf(g_pos[b] * c_invT);
    g_row[b] = log1pf(s2 / s1);   // -log(s1/(s1+s2))
}

// ---------------------------------------------------------------------------
// Kernel 4b: final scalar reduce (32 KB -> 1 float)
// ---------------------------------------------------------------------------
__global__ void k_reduce(float* __restrict__ out) {
    int t = threadIdx.x;
    double acc = 0.0;
    #pragma unroll
    for (int j = 0; j < 32; j++)
        acc += (double)g_row[t + j * 256];
    #pragma unroll
    for (int o = 16; o > 0; o >>= 1) acc += __shfl_xor_sync(0xffffffffu, acc, o);
    __shared__ double sd[8];
    if ((t & 31) == 0) sd[t >> 5] = acc;
    __syncthreads();
    if (t == 0) {
        double tot = 0.0;
        #pragma unroll
        for (int i = 0; i < 8; i++) tot += sd[i];
        out[0] = (float)(tot / (double)B_);
    }
}

// ---------------------------------------------------------------------------
extern "C" void kernel_launch(void* const* d_in, const int* in_sizes, int n_in,
                              void* d_out, int out_size) {
    const float* q = (const float*)d_in[0];
    const float* p = (const float*)d_in[1];
    const float* n = (const float*)d_in[2];
    float* out = (float*)d_out;

    const int smem_bytes = 2 * (BM + BN) * LDA * (int)sizeof(__nv_bfloat16);  // 73728
    cudaFuncSetAttribute(k_gemm, cudaFuncAttributeMaxDynamicSharedMemorySize, smem_bytes);

    k_norm_qp<<<B_, 256>>>(q, p);
    k_norm_n<<<NNEG, 256>>>(n);
    k_gemm<<<dim3(NNEG / BN, B_ / BM), 256, smem_bytes>>>();
    k_rowloss<<<B_ / 256, 256>>>();
    k_reduce<<<1, 256>>>(out);
}